// round 13
// baseline (speedup 1.0000x reference)
#include <cuda_runtime.h>
#include <math.h>

#define H 256
#define W 256
#define NW 8                 // 256 bits per row
#define NPIX (4*H*W)         // 262144
#define NB 128               // 4 batches x 32 col-tiles (8 cols)
#define NT 512

typedef unsigned long long ull;

// ---------------- device state (reset by last block's epilogue) ----------------
__device__ unsigned g_maskb[8][NW][H];   // word-major
__device__ unsigned g_rmax[8];
__device__ unsigned g_rmin[8] = {0x7f7fffffu,0x7f7fffffu,0x7f7fffffu,0x7f7fffffu,
                                 0x7f7fffffu,0x7f7fffffu,0x7f7fffffu,0x7f7fffffu};
__device__ double   g_sums[4];
__device__ unsigned g_bdone[4];      // per-batch: phase-P arrivals (target 32)
__device__ unsigned g_edone[4];      // per-batch: rmax/rmin arrivals (target 32)
__device__ unsigned g_count;

__global__ void __launch_bounds__(NT) k_fused(const float* __restrict__ ypred,
                                              const int*   __restrict__ ytrue,
                                              float*       __restrict__ out) {
    __shared__ __align__(16) struct {
        unsigned bits[2][NW][H];      // 16KB   masks, word-major (conflict-free)
        unsigned colb[2][8][32];      // 2KB    column bitboards per 32-row group
        float    shg[2][8][257];      // 16.4KB horizontal g^2 per image
        unsigned skelw[2][H];         // 2KB    band-coord skeleton word per row
    } S;
    __shared__ float s_red[4][16];
    __shared__ float s_rr[4];

    const int t = threadIdx.x;
    const int lane = t & 31;
    const int bat  = blockIdx.x >> 5;
    const int tile = blockIdx.x & 31;
    const int c0   = tile * 8;
    const int wc0  = c0 >> 5;
    const int imgL = bat * 2, imgP = bat * 2 + 1;
    int shB_ = c0 - 12; if (shB_ < 0) shB_ = 0; if (shB_ > 224) shB_ = 224;
    const int shB = shB_;             // band cols [shB, shB+31]; clamped edges == image edges

    // tile-pixel mapping (used for pp precompute and the sum phase)
    const int c8    = t & 7;
    const int ybase = (t >> 3) * 4;
    const int gc    = c0 + c8;
    const unsigned shbit = gc & 31;
    const unsigned skbit = gc - shB;

    // ================= Phase P: ballots + bit packing (4 px/thread) =========
    {
        int base = blockIdx.x * 2048 + t * 4;
        float4 x4 = *(const float4*)&ypred[base];
        int4   y4 = *(const int4*)&ytrue[base];
        unsigned nibP = (x4.x > 0.f) | ((x4.y > 0.f) << 1) | ((x4.z > 0.f) << 2) | ((x4.w > 0.f) << 3);
        unsigned nibT = (y4.x > 0) | ((y4.y > 0) << 1) | ((y4.z > 0) << 2) | ((y4.w > 0) << 3);
        unsigned sh = (lane & 7) * 4;
        unsigned wP = nibP << sh, wT = nibT << sh;
        #pragma unroll
        for (int o = 1; o < 8; o <<= 1) {
            wP |= __shfl_xor_sync(0xffffffffu, wP, o);
            wT |= __shfl_xor_sync(0xffffffffu, wT, o);
        }
        if ((lane & 7) == 0) {
            int row = (base >> 8) & 255, word = (base & 255) >> 5;
            g_maskb[imgL][word][row] = wT;
            g_maskb[imgP][word][row] = wP;
        }
    }
    // ---- per-batch barrier 1: arrive, overlap pp compute, then poll --------
    __syncthreads();
    if (t == 0) {
        __threadfence();
        atomicAdd(&g_bdone[bat], 1u);
    }
    // overlap: pp for this thread's 4 sum-phase pixels (depends only on ypred)
    float pp[4];
    #pragma unroll
    for (int k = 0; k < 4; k++) {
        float x = __ldg(&ypred[bat * 65536 + (ybase + k) * 256 + gc]);
        float p = __fdividef(1.0f, 1.0f + __expf(-x));
        pp[k]   = __fdividef(1.0f, 1.0f + __expf(1.0f - 2.0f * p));
    }
    if (t == 0) {
        volatile unsigned* vb = &g_bdone[bat];
        while (*vb < 32u) __nanosleep(32);
        __threadfence();
    }
    __syncthreads();

    {   // load both bitboards (vectorized; imgP contiguous after imgL)
        uint4* dst = (uint4*)&S.bits[0][0][0];
        const uint4* src = (const uint4*)&g_maskb[imgL][0][0];
        #pragma unroll
        for (int j = 0; j < 2; j++) dst[t + j * NT] = src[t + j * NT];
    }
    __syncthreads();

    // ===== Phase 3: per (img,row): ballot-transpose band + branch-free hEDT ==
    {
        const int im = t >> 8;            // 0: true, 1: pred
        const int r  = t & 255;
        const int grp = (t >> 5) & 7;     // 32-row group, lane = r&31

        const int ws = shB >> 5, so = shB & 31;
        unsigned lo = S.bits[im][ws][r];
        unsigned hi = (ws < 7) ? S.bits[im][ws + 1][r] : 0u;
        unsigned band = __funnelshift_r(lo, hi, so);

        // ballot transpose: lane l keeps column l's 32-row word for this group
        unsigned keep = 0u;
        #pragma unroll
        for (int l = 0; l < 32; l++) {
            unsigned bw = __ballot_sync(0xffffffffu, (band >> l) & 1u);
            if (lane == l) keep = bw;
        }
        S.colb[im][grp][lane] = keep;

        // branch-free horizontal EDT: prefix/suffix nearest-zero over words
        unsigned z[NW];
        #pragma unroll
        for (int w = 0; w < NW; w++) z[w] = ~S.bits[im][w][r];
        int nzl = -512;
        for (int w = 0; w < wc0; w++) {
            unsigned v = z[w];
            nzl = v ? (w * 32 + 31 - __clz(v)) : nzl;
        }
        int nzr = 1024;
        for (int w = 7; w > wc0; w--) {
            unsigned v = z[w];
            nzr = v ? (w * 32 + __ffs(v) - 1) : nzr;
        }
        unsigned zown = z[wc0];
        #pragma unroll
        for (int k = 0; k < 8; k++) {
            int c = c0 + k, kk = c & 31;
            unsigned vlo = zown & (0xffffffffu >> (31 - kk));
            unsigned vhi = zown & (0xffffffffu << kk);
            int posl = vlo ? (wc0 * 32 + 31 - __clz(vlo)) : nzl;
            int posr = vhi ? (wc0 * 32 + __ffs(vhi) - 1) : nzr;
            int g = min(min(c - posl, posr - c), 512);
            S.shg[im][k][r] = (float)(g * g);
        }
    }
    __syncthreads();

    // ===== Phase 4: register-resident warp skeleton (no block barriers) =====
    {
        const int wid = t >> 5;           // 16 warps
        const int im  = wid >> 3;
        const int w   = wid & 7;          // 32-row strip

        unsigned up  = (w > 0) ? S.colb[im][w - 1][lane] : 0u;
        unsigned mid =           S.colb[im][w    ][lane];
        unsigned dn  = (w < 7) ? S.colb[im][w + 1][lane] : 0u;
        ull cur = ((ull)(up >> 20)) | ((ull)mid << 12) | ((ull)(dn & 0xFFFu) << 44);
        ull skel = 0ULL;

        #pragma unroll 1
        for (int it = 0; it < 11; it++) {
            ull vu = cur << 1;
            if (w == 0) vu |= (1ULL << 12);
            ull vd = cur >> 1;
            if (w == 7) vd |= (1ULL << 43);
            ull lf = __shfl_up_sync(0xffffffffu, cur, 1);
            if (lane == 0)  lf = ~0ULL;
            ull rt = __shfl_down_sync(0xffffffffu, cur, 1);
            if (lane == 31) rt = ~0ULL;
            ull e = cur & vu & vd & lf & rt;

            ull vo = e | (e << 1) | (e >> 1);
            ull lo_ = __shfl_up_sync(0xffffffffu, vo, 1);
            if (lane == 0)  lo_ = 0ULL;
            ull ro_ = __shfl_down_sync(0xffffffffu, vo, 1);
            if (lane == 31) ro_ = 0ULL;
            skel |= cur & ~(vo | lo_ | ro_);
            cur = e;
        }
        unsigned mysk = 0u;
        #pragma unroll
        for (int k = 0; k < 32; k++) {
            unsigned bw = __ballot_sync(0xffffffffu, (unsigned)((skel >> (12 + k)) & 1ULL));
            if (lane == k) mysk = bw;
        }
        S.skelw[im][w * 32 + lane] = mysk;
        // NO sync here: vEDT doesn't read skelw; sync deferred until minmax
    }

    // ---- vertical envelope: 4 rows/thread, both images, spec unroll-4 ------
    const float* cp0 = &S.shg[0][c8][0];
    const float* cp1 = &S.shg[1][c8][0];
    float dm0[4], dm1[4];
    #pragma unroll 1
    for (int k = 0; k < 4; k++) {
        int y = ybase + k;
        float m0 = cp0[y], m1 = cp1[y];
        int dy = 1;
        while ((float)(dy * dy) < fmaxf(m0, m1) && dy < H) {
            #pragma unroll
            for (int j = 0; j < 4; j++) {          // clamped = safe overestimates
                int d = dy + j;
                float d2 = (float)(d * d);
                int ya = y - d; ya = ya < 0 ? 0 : ya;
                int yb = y + d; yb = yb > H - 1 ? H - 1 : yb;
                m0 = fminf(m0, fminf(cp0[ya], cp0[yb]) + d2);
                m1 = fminf(m1, fminf(cp1[ya], cp1[yb]) + d2);
            }
            dy += 4;
        }
        unsigned mb0 = (S.bits[0][wc0][y] >> shbit) & 1u;
        unsigned mb1 = (S.bits[1][wc0][y] >> shbit) & 1u;
        dm0[k] = mb0 ? sqrtf(m0) : 0.0f;
        dm1[k] = mb1 ? sqrtf(m1) : 0.0f;
    }
    __syncthreads();                     // skelw now visible to all

    // ---- tile rmax/rmin for both images + per-batch barrier (overlapped) ----
    {
        float mxL = 0.f, mnL = __int_as_float(0x7f7fffff);
        float mxP = 0.f, mnP = __int_as_float(0x7f7fffff);
        #pragma unroll
        for (int k = 0; k < 4; k++) {
            int y = ybase + k;
            float srL = ((S.skelw[0][y] >> skbit) & 1u) ? dm0[k] : 0.f;
            float srP = ((S.skelw[1][y] >> skbit) & 1u) ? dm1[k] : 0.f;
            mxL = fmaxf(mxL, srL); mnL = fminf(mnL, srL);
            mxP = fmaxf(mxP, srP); mnP = fminf(mnP, srP);
        }
        #pragma unroll
        for (int o = 16; o; o >>= 1) {
            mxL = fmaxf(mxL, __shfl_xor_sync(0xffffffffu, mxL, o));
            mnL = fminf(mnL, __shfl_xor_sync(0xffffffffu, mnL, o));
            mxP = fmaxf(mxP, __shfl_xor_sync(0xffffffffu, mxP, o));
            mnP = fminf(mnP, __shfl_xor_sync(0xffffffffu, mnP, o));
        }
        if (lane == 0) {
            int w = t >> 5;
            s_red[0][w] = mxL; s_red[1][w] = mnL; s_red[2][w] = mxP; s_red[3][w] = mnP;
        }
        __syncthreads();
        if (t == 0) {
            float a = s_red[0][0], b = s_red[1][0], c = s_red[2][0], d = s_red[3][0];
            #pragma unroll
            for (int w = 1; w < 16; w++) {
                a = fmaxf(a, s_red[0][w]); b = fminf(b, s_red[1][w]);
                c = fmaxf(c, s_red[2][w]); d = fminf(d, s_red[3][w]);
            }
            atomicMax(&g_rmax[imgL], __float_as_uint(a));
            atomicMin(&g_rmin[imgL], __float_as_uint(b));
            atomicMax(&g_rmax[imgP], __float_as_uint(c));
            atomicMin(&g_rmin[imgP], __float_as_uint(d));
            __threadfence();
            atomicAdd(&g_edone[bat], 1u);
            volatile unsigned* eb = &g_edone[bat];
            while (*eb < 32u) __nanosleep(32);
            __threadfence();
            s_rr[0] = fmaxf(__uint_as_float(*(volatile unsigned*)&g_rmax[imgL]), 1.0f);
            s_rr[1] = fmaxf(__uint_as_float(*(volatile unsigned*)&g_rmin[imgL]), 1.0f);
            s_rr[2] = fmaxf(__uint_as_float(*(volatile unsigned*)&g_rmax[imgP]), 1.0f);
            s_rr[3] = fmaxf(__uint_as_float(*(volatile unsigned*)&g_rmin[imgP]), 1.0f);
        }
        __syncthreads();
    }
    const float rmaxL = s_rr[0], rminL = s_rr[1], rmaxP = s_rr[2], rminP = s_rr[3];
    const float irL = __fdividef(1.0f, rmaxL), irP = __fdividef(1.0f, rmaxP);

    // ---- q-maps + partial sums (pp already in registers) ----
    float t1 = 0.f, d1 = 0.f, t2 = 0.f, d2s = 0.f;
    #pragma unroll
    for (int k = 0; k < 4; k++) {
        int y = ybase + k;
        bool mL = (S.bits[0][wc0][y] >> shbit) & 1u;
        bool mP = (S.bits[1][wc0][y] >> shbit) & 1u;
        bool sL = (S.skelw[0][y] >> skbit) & 1u;
        bool sP = (S.skelw[1][y] >> skbit) & 1u;
        float dl = dm0[k], dp = dm1[k];
        float ppx = pp[k];

        float q_vl   = mL ? fminf(dl, rmaxL) * irL : 0.f;
        float q_slvl = sL ? dl * irL : 0.f;
        float q_sl   = sL ? (rmaxL - dl + rminL) * irL : 0.f;
        float q_vp   = mP ? fminf(dp, rmaxP) * irP * ppx : 0.f;
        float q_spvp = sP ? dp * irP * ppx : 0.f;
        float q_sp   = sP ? (rmaxP - dp + rminP) * irP * ppx : 0.f;
        t1  += q_sp * q_vl;
        d1  += (sP && !sL) ? q_spvp * q_sp : q_slvl * q_sp;   // combine_tensors
        t2  += q_sl * q_vp;
        d2s += (sL && !sP) ? q_slvl * q_sl : q_spvp * q_sl;
    }
    #pragma unroll
    for (int o = 16; o; o >>= 1) {
        t1  += __shfl_xor_sync(0xffffffffu, t1,  o);
        d1  += __shfl_xor_sync(0xffffffffu, d1,  o);
        t2  += __shfl_xor_sync(0xffffffffu, t2,  o);
        d2s += __shfl_xor_sync(0xffffffffu, d2s, o);
    }
    if (lane == 0) {
        int w = t >> 5;
        s_red[0][w] = t1; s_red[1][w] = d1; s_red[2][w] = t2; s_red[3][w] = d2s;
    }
    __syncthreads();
    if (t == 0) {
        double a0 = 0.0, a1 = 0.0, a2 = 0.0, a3 = 0.0;
        #pragma unroll
        for (int w = 0; w < 16; w++) {
            a0 += (double)s_red[0][w]; a1 += (double)s_red[1][w];
            a2 += (double)s_red[2][w]; a3 += (double)s_red[3][w];
        }
        atomicAdd(&g_sums[0], a0);
        atomicAdd(&g_sums[1], a1);
        atomicAdd(&g_sums[2], a2);
        atomicAdd(&g_sums[3], a3);
        __threadfence();
        unsigned done = atomicAdd(&g_count, 1u);
        if (done == NB - 1) {                      // last block: epilogue + reset
            double S1 = atomicAdd(&g_sums[0], 0.0);
            double D1 = atomicAdd(&g_sums[1], 0.0);
            double S2 = atomicAdd(&g_sums[2], 0.0);
            double D2 = atomicAdd(&g_sums[3], 0.0);
            double wp = (S1 + 1.0) / (D1 + 1.0);
            double ws = (S2 + 1.0) / (D2 + 1.0);
            out[0] = (float)(1.0 - 2.0 * (wp * ws) / (wp + ws));
            g_count = 0u;
            #pragma unroll
            for (int i = 0; i < 4; i++) { g_bdone[i] = 0u; g_edone[i] = 0u; g_sums[i] = 0.0; }
            #pragma unroll
            for (int i = 0; i < 8; i++) { g_rmax[i] = 0u; g_rmin[i] = 0x7f7fffffu; }
            __threadfence();
        }
    }
}

// ---------------- launch ----------------
extern "C" void kernel_launch(void* const* d_in, const int* in_sizes, int n_in,
                              void* d_out, int out_size) {
    const float* ypred = (const float*)d_in[0];
    const int*   ytrue = (const int*)d_in[1];
    float*       out   = (float*)d_out;
    k_fused<<<NB, NT>>>(ypred, ytrue, out);
}

// round 14
// speedup vs baseline: 1.2301x; 1.2301x over previous
#include <cuda_runtime.h>
#include <math.h>

#define H 256
#define W 256
#define NW 8                 // 256 bits per row
#define NPIX (4*H*W)         // 262144
#define NB 128               // 4 batches x 32 col-tiles (8 cols)
#define NT 512

typedef unsigned long long ull;

// 32x32 bit-matrix transpose within a warp: lane r holds row r; returns column lane.
__device__ __forceinline__ unsigned bit_transpose32(unsigned x, int lane) {
    const unsigned HM[5] = {0xFFFF0000u, 0xFF00FF00u, 0xF0F0F0F0u, 0xCCCCCCCCu, 0xAAAAAAAAu};
    int s = 16;
    #pragma unroll
    for (int i = 0; i < 5; i++, s >>= 1) {
        unsigned hm = HM[i];
        unsigned y = __shfl_xor_sync(0xffffffffu, x, s);
        x = (lane & s) ? ((x & hm) | ((y >> s) & ~hm))
                       : ((x & ~hm) | ((y << s) & hm));
    }
    return x;
}

// ---------------- device state (reset by last block's epilogue) ----------------
__device__ unsigned g_maskb[8][NW][H];   // word-major
__device__ unsigned g_rmax[8];
__device__ unsigned g_rmin[8] = {0x7f7fffffu,0x7f7fffffu,0x7f7fffffu,0x7f7fffffu,
                                 0x7f7fffffu,0x7f7fffffu,0x7f7fffffu,0x7f7fffffu};
__device__ double   g_sums[4];
__device__ unsigned g_bdone[4];      // per-batch: phase-P arrivals (target 32)
__device__ unsigned g_edone[4];      // per-batch: rmax/rmin arrivals (target 32)
__device__ unsigned g_count;

__global__ void __launch_bounds__(NT) k_fused(const float* __restrict__ ypred,
                                              const int*   __restrict__ ytrue,
                                              float*       __restrict__ out) {
    __shared__ __align__(16) struct {
        unsigned bits[2][NW][H];      // 16KB   masks, word-major (conflict-free)
        unsigned colb[2][8][32];      // 2KB    column bitboards per 32-row group
        float    shg[2][8][257];      // 16.4KB horizontal g^2 per image
        unsigned skelw[2][H];         // 2KB    band-coord skeleton word per row
    } S;
    __shared__ float s_red[4][16];
    __shared__ float s_rr[4];

    const int t = threadIdx.x;
    const int lane = t & 31;
    const int bat  = blockIdx.x >> 5;
    const int tile = blockIdx.x & 31;
    const int c0   = tile * 8;
    const int wc0  = c0 >> 5;
    const int imgL = bat * 2, imgP = bat * 2 + 1;
    int shB_ = c0 - 12; if (shB_ < 0) shB_ = 0; if (shB_ > 224) shB_ = 224;
    const int shB = shB_;             // band cols [shB, shB+31]; clamped edges == image edges

    const int c8    = t & 7;
    const int ybase = (t >> 3) * 4;
    const int gc    = c0 + c8;
    const unsigned shbit = gc & 31;
    const unsigned skbit = gc - shB;

    // ================= Phase P: ballots + bit packing (4 px/thread) =========
    {
        int base = blockIdx.x * 2048 + t * 4;
        float4 x4 = *(const float4*)&ypred[base];
        int4   y4 = *(const int4*)&ytrue[base];
        unsigned nibP = (x4.x > 0.f) | ((x4.y > 0.f) << 1) | ((x4.z > 0.f) << 2) | ((x4.w > 0.f) << 3);
        unsigned nibT = (y4.x > 0) | ((y4.y > 0) << 1) | ((y4.z > 0) << 2) | ((y4.w > 0) << 3);
        unsigned sh = (lane & 7) * 4;
        unsigned wP = nibP << sh, wT = nibT << sh;
        #pragma unroll
        for (int o = 1; o < 8; o <<= 1) {
            wP |= __shfl_xor_sync(0xffffffffu, wP, o);
            wT |= __shfl_xor_sync(0xffffffffu, wT, o);
        }
        if ((lane & 7) == 0) {
            int row = (base >> 8) & 255, word = (base & 255) >> 5;
            g_maskb[imgL][word][row] = wT;
            g_maskb[imgP][word][row] = wP;
        }
    }
    // ---- per-batch barrier 1: arrive, overlap pp compute, then poll --------
    __syncthreads();
    if (t == 0) {
        __threadfence();
        atomicAdd(&g_bdone[bat], 1u);
    }
    float pp[4];
    #pragma unroll
    for (int k = 0; k < 4; k++) {
        float x = __ldg(&ypred[bat * 65536 + (ybase + k) * 256 + gc]);
        float p = __fdividef(1.0f, 1.0f + __expf(-x));
        pp[k]   = __fdividef(1.0f, 1.0f + __expf(1.0f - 2.0f * p));
    }
    if (t == 0) {
        volatile unsigned* vb = &g_bdone[bat];
        while (*vb < 32u) __nanosleep(32);
        __threadfence();
    }
    __syncthreads();

    {   // load both bitboards (vectorized; imgP contiguous after imgL)
        uint4* dst = (uint4*)&S.bits[0][0][0];
        const uint4* src = (const uint4*)&g_maskb[imgL][0][0];
        #pragma unroll
        for (int j = 0; j < 2; j++) dst[t + j * NT] = src[t + j * NT];
    }
    __syncthreads();

    // ===== Phase 3: per (img,row): butterfly-transpose band + branch-free hEDT
    {
        const int im = t >> 8;            // 0: true, 1: pred
        const int r  = t & 255;
        const int grp = (t >> 5) & 7;

        const int ws = shB >> 5, so = shB & 31;
        unsigned lo = S.bits[im][ws][r];
        unsigned hi = (ws < 7) ? S.bits[im][ws + 1][r] : 0u;
        unsigned band = __funnelshift_r(lo, hi, so);

        S.colb[im][grp][lane] = bit_transpose32(band, lane);

        // branch-free horizontal EDT: prefix/suffix nearest-zero over words
        unsigned z[NW];
        #pragma unroll
        for (int w = 0; w < NW; w++) z[w] = ~S.bits[im][w][r];
        int nzl = -512;
        for (int w = 0; w < wc0; w++) {
            unsigned v = z[w];
            nzl = v ? (w * 32 + 31 - __clz(v)) : nzl;
        }
        int nzr = 1024;
        for (int w = 7; w > wc0; w--) {
            unsigned v = z[w];
            nzr = v ? (w * 32 + __ffs(v) - 1) : nzr;
        }
        unsigned zown = z[wc0];
        #pragma unroll
        for (int k = 0; k < 8; k++) {
            int c = c0 + k, kk = c & 31;
            unsigned vlo = zown & (0xffffffffu >> (31 - kk));
            unsigned vhi = zown & (0xffffffffu << kk);
            int posl = vlo ? (wc0 * 32 + 31 - __clz(vlo)) : nzl;
            int posr = vhi ? (wc0 * 32 + __ffs(vhi) - 1) : nzr;
            int g = min(min(c - posl, posr - c), 512);
            S.shg[im][k][r] = (float)(g * g);
        }
    }
    __syncthreads();

    // ===== Phase 4: register-resident warp skeleton (no block barriers) =====
    {
        const int wid = t >> 5;
        const int im  = wid >> 3;
        const int w   = wid & 7;

        unsigned up  = (w > 0) ? S.colb[im][w - 1][lane] : 0u;
        unsigned mid =           S.colb[im][w    ][lane];
        unsigned dn  = (w < 7) ? S.colb[im][w + 1][lane] : 0u;
        ull cur = ((ull)(up >> 20)) | ((ull)mid << 12) | ((ull)(dn & 0xFFFu) << 44);
        ull skel = 0ULL;

        #pragma unroll 1
        for (int it = 0; it < 11; it++) {
            ull vu = cur << 1;
            if (w == 0) vu |= (1ULL << 12);
            ull vd = cur >> 1;
            if (w == 7) vd |= (1ULL << 43);
            ull lf = __shfl_up_sync(0xffffffffu, cur, 1);
            if (lane == 0)  lf = ~0ULL;
            ull rt = __shfl_down_sync(0xffffffffu, cur, 1);
            if (lane == 31) rt = ~0ULL;
            ull e = cur & vu & vd & lf & rt;

            ull vo = e | (e << 1) | (e >> 1);
            ull lo_ = __shfl_up_sync(0xffffffffu, vo, 1);
            if (lane == 0)  lo_ = 0ULL;
            ull ro_ = __shfl_down_sync(0xffffffffu, vo, 1);
            if (lane == 31) ro_ = 0ULL;
            skel |= cur & ~(vo | lo_ | ro_);
            cur = e;
        }
        unsigned own32 = (unsigned)(skel >> 12);           // lane=col, bit=own row
        S.skelw[im][w * 32 + lane] = bit_transpose32(own32, lane);
    }

    // ---- vertical envelope: 2 rows x 2 images per while-loop --------------
    const float* cp0 = &S.shg[0][c8][0];
    const float* cp1 = &S.shg[1][c8][0];
    float dm0[4], dm1[4];
    #pragma unroll
    for (int kp = 0; kp < 2; kp++) {
        const int y0 = ybase + kp * 2, y1 = y0 + 1;
        float m00 = cp0[y0], m01 = cp0[y1];
        float m10 = cp1[y0], m11 = cp1[y1];
        int dy = 1;
        while (dy < H) {
            float mm = fmaxf(fmaxf(m00, m01), fmaxf(m10, m11));
            if ((float)(dy * dy) >= mm) break;
            #pragma unroll
            for (int j = 0; j < 4; j++) {
                int d = dy + j;
                float d2 = (float)(d * d);
                int ya0 = y0 - d; ya0 = ya0 < 0 ? 0 : ya0;
                int yb0 = y0 + d; yb0 = yb0 > H - 1 ? H - 1 : yb0;
                int ya1 = y1 - d; ya1 = ya1 < 0 ? 0 : ya1;
                int yb1 = y1 + d; yb1 = yb1 > H - 1 ? H - 1 : yb1;
                m00 = fminf(m00, fminf(cp0[ya0], cp0[yb0]) + d2);
                m01 = fminf(m01, fminf(cp0[ya1], cp0[yb1]) + d2);
                m10 = fminf(m10, fminf(cp1[ya0], cp1[yb0]) + d2);
                m11 = fminf(m11, fminf(cp1[ya1], cp1[yb1]) + d2);
            }
            dy += 4;
        }
        unsigned a0 = (S.bits[0][wc0][y0] >> shbit) & 1u;
        unsigned a1 = (S.bits[0][wc0][y1] >> shbit) & 1u;
        unsigned b0 = (S.bits[1][wc0][y0] >> shbit) & 1u;
        unsigned b1 = (S.bits[1][wc0][y1] >> shbit) & 1u;
        dm0[kp * 2 + 0] = a0 ? sqrtf(m00) : 0.0f;
        dm0[kp * 2 + 1] = a1 ? sqrtf(m01) : 0.0f;
        dm1[kp * 2 + 0] = b0 ? sqrtf(m10) : 0.0f;
        dm1[kp * 2 + 1] = b1 ? sqrtf(m11) : 0.0f;
    }
    __syncthreads();                     // skelw now visible to all

    // ---- tile rmax/rmin for both images + per-batch barrier ----------------
    {
        float mxL = 0.f, mnL = __int_as_float(0x7f7fffff);
        float mxP = 0.f, mnP = __int_as_float(0x7f7fffff);
        #pragma unroll
        for (int k = 0; k < 4; k++) {
            int y = ybase + k;
            float srL = ((S.skelw[0][y] >> skbit) & 1u) ? dm0[k] : 0.f;
            float srP = ((S.skelw[1][y] >> skbit) & 1u) ? dm1[k] : 0.f;
            mxL = fmaxf(mxL, srL); mnL = fminf(mnL, srL);
            mxP = fmaxf(mxP, srP); mnP = fminf(mnP, srP);
        }
        #pragma unroll
        for (int o = 16; o; o >>= 1) {
            mxL = fmaxf(mxL, __shfl_xor_sync(0xffffffffu, mxL, o));
            mnL = fminf(mnL, __shfl_xor_sync(0xffffffffu, mnL, o));
            mxP = fmaxf(mxP, __shfl_xor_sync(0xffffffffu, mxP, o));
            mnP = fminf(mnP, __shfl_xor_sync(0xffffffffu, mnP, o));
        }
        if (lane == 0) {
            int w = t >> 5;
            s_red[0][w] = mxL; s_red[1][w] = mnL; s_red[2][w] = mxP; s_red[3][w] = mnP;
        }
        __syncthreads();
        if (t == 0) {
            float a = s_red[0][0], b = s_red[1][0], c = s_red[2][0], d = s_red[3][0];
            #pragma unroll
            for (int w = 1; w < 16; w++) {
                a = fmaxf(a, s_red[0][w]); b = fminf(b, s_red[1][w]);
                c = fmaxf(c, s_red[2][w]); d = fminf(d, s_red[3][w]);
            }
            atomicMax(&g_rmax[imgL], __float_as_uint(a));
            atomicMin(&g_rmin[imgL], __float_as_uint(b));
            atomicMax(&g_rmax[imgP], __float_as_uint(c));
            atomicMin(&g_rmin[imgP], __float_as_uint(d));
            __threadfence();
            atomicAdd(&g_edone[bat], 1u);
        }
        if (t < 4) {                     // 4 pollers/readers: parallel L2 loads
            volatile unsigned* eb = &g_edone[bat];
            while (*eb < 32u) __nanosleep(32);
            __threadfence();
            unsigned v = (t == 0) ? *(volatile unsigned*)&g_rmax[imgL]
                       : (t == 1) ? *(volatile unsigned*)&g_rmin[imgL]
                       : (t == 2) ? *(volatile unsigned*)&g_rmax[imgP]
                                  : *(volatile unsigned*)&g_rmin[imgP];
            s_rr[t] = fmaxf(__uint_as_float(v), 1.0f);
        }
        __syncthreads();
    }
    const float rmaxL = s_rr[0], rminL = s_rr[1], rmaxP = s_rr[2], rminP = s_rr[3];
    const float irL = __fdividef(1.0f, rmaxL), irP = __fdividef(1.0f, rmaxP);

    // ---- q-maps + partial sums (pp already in registers) ----
    float t1 = 0.f, d1 = 0.f, t2 = 0.f, d2s = 0.f;
    #pragma unroll
    for (int k = 0; k < 4; k++) {
        int y = ybase + k;
        bool mL = (S.bits[0][wc0][y] >> shbit) & 1u;
        bool mP = (S.bits[1][wc0][y] >> shbit) & 1u;
        bool sL = (S.skelw[0][y] >> skbit) & 1u;
        bool sP = (S.skelw[1][y] >> skbit) & 1u;
        float dl = dm0[k], dp = dm1[k];
        float ppx = pp[k];

        float q_vl   = mL ? fminf(dl, rmaxL) * irL : 0.f;
        float q_slvl = sL ? dl * irL : 0.f;
        float q_sl   = sL ? (rmaxL - dl + rminL) * irL : 0.f;
        float q_vp   = mP ? fminf(dp, rmaxP) * irP * ppx : 0.f;
        float q_spvp = sP ? dp * irP * ppx : 0.f;
        float q_sp   = sP ? (rmaxP - dp + rminP) * irP * ppx : 0.f;
        t1  += q_sp * q_vl;
        d1  += (sP && !sL) ? q_spvp * q_sp : q_slvl * q_sp;   // combine_tensors
        t2  += q_sl * q_vp;
        d2s += (sL && !sP) ? q_slvl * q_sl : q_spvp * q_sl;
    }
    #pragma unroll
    for (int o = 16; o; o >>= 1) {
        t1  += __shfl_xor_sync(0xffffffffu, t1,  o);
        d1  += __shfl_xor_sync(0xffffffffu, d1,  o);
        t2  += __shfl_xor_sync(0xffffffffu, t2,  o);
        d2s += __shfl_xor_sync(0xffffffffu, d2s, o);
    }
    if (lane == 0) {
        int w = t >> 5;
        s_red[0][w] = t1; s_red[1][w] = d1; s_red[2][w] = t2; s_red[3][w] = d2s;
    }
    __syncthreads();
    // ---- parallel tail: threads 0..3 each reduce + atomic one sum ----------
    if (t < 4) {
        double a = 0.0;
        #pragma unroll
        for (int w = 0; w < 16; w++) a += (double)s_red[t][w];
        atomicAdd(&g_sums[t], a);
        __threadfence();
    }
    __syncthreads();
    if (t == 0) {
        __threadfence();
        unsigned done = atomicAdd(&g_count, 1u);
        if (done == NB - 1) {                      // last block: epilogue + reset
            __threadfence();
            volatile double* gs = g_sums;          // 4 independent L2 loads (MLP)
            double S1 = gs[0], D1 = gs[1], S2 = gs[2], D2 = gs[3];
            double wp = (S1 + 1.0) / (D1 + 1.0);
            double ws = (S2 + 1.0) / (D2 + 1.0);
            out[0] = (float)(1.0 - 2.0 * (wp * ws) / (wp + ws));
            g_count = 0u;
            #pragma unroll
            for (int i = 0; i < 4; i++) { g_bdone[i] = 0u; g_edone[i] = 0u; g_sums[i] = 0.0; }
            #pragma unroll
            for (int i = 0; i < 8; i++) { g_rmax[i] = 0u; g_rmin[i] = 0x7f7fffffu; }
            __threadfence();
        }
    }
}

// ---------------- launch ----------------
extern "C" void kernel_launch(void* const* d_in, const int* in_sizes, int n_in,
                              void* d_out, int out_size) {
    const float* ypred = (const float*)d_in[0];
    const int*   ytrue = (const int*)d_in[1];
    float*       out   = (float*)d_out;
    k_fused<<<NB, NT>>>(ypred, ytrue, out);
}